// round 6
// baseline (speedup 1.0000x reference)
#include <cuda_runtime.h>
#include <cuda_bf16.h>
#include <cstdint>

#define NBATCH 8
#define CDIM   256
#define TDIM   16384
#define DCODES 512
#define BT     128
#define NTHREADS 512
#define MARGIN 0.125f

// ---- smem byte layout ----
// Ah[4 kchunks][128 t][72 bf16-slots]; row stride 144 B
#define AK        18432                 // 128*144
#define OFF_B     73728                 // B double buffer (= 4*AK)
#define BSTAGE    36864                 // per stage: Bh 18432 + Bm 18432
#define OFF_HN    147456                // float[512] hnorm copy
#define OFF_FIDX  149504
#define OFF_SIDXM 150016
#define OFF_FLAGS 150528
#define OFF_FLAGN 151040
#define SMEM_BYTES 151072
// overlays (A region, dead after mainloop): bestv[128][16]@0, secv@8192,
// ibv@16384, isv@24576; later rowsT[256][132] f32 @0 (135168 B < 147456)
#define RT_STRIDE 132

__device__ float g_hnorm[DCODES];
__device__ __align__(256) __nv_bfloat16 g_dh16[DCODES * CDIM];
__device__ __align__(256) __nv_bfloat16 g_dm16[DCODES * CDIM];

// ---------------- helpers ----------------
__device__ __forceinline__ uint32_t smem_u32(const void* p) {
    uint32_t a;
    asm("{ .reg .u64 t; cvta.to.shared.u64 t, %1; cvt.u32.u64 %0, t; }" : "=r"(a) : "l"(p));
    return a;
}
__device__ __forceinline__ void ldmx4(uint32_t r[4], uint32_t addr) {
    asm volatile("ldmatrix.sync.aligned.m8n8.x4.shared.b16 {%0,%1,%2,%3}, [%4];"
                 : "=r"(r[0]), "=r"(r[1]), "=r"(r[2]), "=r"(r[3]) : "r"(addr));
}
__device__ __forceinline__ void mma16816(float c[4], const uint32_t a[4], const uint32_t b[2]) {
    asm volatile("mma.sync.aligned.m16n8k16.row.col.f32.bf16.bf16.f32 "
                 "{%0,%1,%2,%3}, {%4,%5,%6,%7}, {%8,%9}, {%0,%1,%2,%3};"
                 : "+f"(c[0]), "+f"(c[1]), "+f"(c[2]), "+f"(c[3])
                 : "r"(a[0]), "r"(a[1]), "r"(a[2]), "r"(a[3]), "r"(b[0]), "r"(b[1]));
}
#define CPA16(dst, src) \
    asm volatile("cp.async.cg.shared.global [%0], [%1], 16;" :: "r"(dst), "l"(src) : "memory")
#define CPA_COMMIT() asm volatile("cp.async.commit_group;" ::: "memory")
#define CPA_WAIT0()  asm volatile("cp.async.wait_group 0;" ::: "memory")

// ---------------- prologue kernels ----------------
__global__ void vq_hnorm_kernel(const float* __restrict__ dict) {
    const int wid = threadIdx.x >> 5, lane = threadIdx.x & 31;
    const int d = blockIdx.x * 8 + wid;
    const float4* row = reinterpret_cast<const float4*>(dict + (size_t)d * CDIM);
    float s = 0.f;
#pragma unroll
    for (int j = 0; j < 2; j++) {
        float4 v = row[lane + 32 * j];
        s += v.x * v.x + v.y * v.y + v.z * v.z + v.w * v.w;
    }
#pragma unroll
    for (int o = 16; o; o >>= 1) s += __shfl_xor_sync(0xffffffffu, s, o);
    if (lane == 0) g_hnorm[d] = 0.5f * s;
}

__global__ void vq_split_kernel(const float* __restrict__ dict) {
    int idx = blockIdx.x * blockDim.x + threadIdx.x;   // 0..65535
    int d = idx >> 7, j = idx & 127;
    float x0 = dict[(size_t)d * CDIM + 2 * j];
    float x1 = dict[(size_t)d * CDIM + 2 * j + 1];
    __nv_bfloat162 h2 = __float22bfloat162_rn(make_float2(x0, x1));
    float2 hf = __bfloat1622float2(h2);
    __nv_bfloat162 m2 = __float22bfloat162_rn(make_float2(x0 - hf.x, x1 - hf.y));
    reinterpret_cast<uint32_t*>(g_dh16)[d * 128 + j] = *reinterpret_cast<uint32_t*>(&h2);
    reinterpret_cast<uint32_t*>(g_dm16)[d * 128 + j] = *reinterpret_cast<uint32_t*>(&m2);
}

// ---------------- main kernel ----------------
__global__ __launch_bounds__(NTHREADS, 1)
void vq_main_kernel(const float* __restrict__ inputs,
                    const float* __restrict__ dict,
                    float* __restrict__ out) {
    extern __shared__ float smem[];
    const uint32_t sbase = smem_u32(smem);
    char* smc = reinterpret_cast<char*>(smem);
    float* shn   = reinterpret_cast<float*>(smc + OFF_HN);
    int*   fidx  = reinterpret_cast<int*>(smc + OFF_FIDX);
    int*   sidxm = reinterpret_cast<int*>(smc + OFF_SIDXM);
    int*   flags = reinterpret_cast<int*>(smc + OFF_FLAGS);
    int*   flagn = reinterpret_cast<int*>(smc + OFF_FLAGN);

    const int tid = threadIdx.x;
    const int wid = tid >> 5, lane = tid & 31;
    const int wm = wid >> 2, wn = wid & 3;           // 4 x 4 warp grid
    const int n = blockIdx.x >> 7, tt0 = (blockIdx.x & 127) << 7;
    const size_t E = (size_t)NBATCH * CDIM * TDIM;

    if (tid == 0) *flagn = 0;
    if (tid < DCODES) shn[tid] = g_hnorm[tid];       // 512 threads, one shot

    // ================= A build: load x slabs, transpose + bf16-hi into Ah =================
    {
        float* xsl = smem + OFF_B / 4;     // slab [64 c][128 t] fp32 in B region
        const int t = tid & 127, quarter = tid >> 7;    // 0..3
        for (int kc = 0; kc < 4; kc++) {
#pragma unroll
            for (int it = 0; it < 4; it++) {
                int j = tid + it * 512;
                int c = j >> 5, u = j & 31;
                const float* src = inputs + ((size_t)(n * CDIM + kc * 64 + c)) * TDIM + tt0 + u * 4;
                CPA16(sbase + OFF_B + c * 512 + u * 16, src);
            }
            CPA_COMMIT(); CPA_WAIT0();
            __syncthreads();
#pragma unroll
            for (int i = 0; i < 8; i++) {
                int c = quarter * 16 + 2 * i;
                float x0 = xsl[c * 128 + t];
                float x1 = xsl[(c + 1) * 128 + t];
                __nv_bfloat162 h2 = __float22bfloat162_rn(make_float2(x0, x1));
                *reinterpret_cast<uint32_t*>(smc + kc * AK + t * 144 + c * 2) =
                    *reinterpret_cast<uint32_t*>(&h2);
            }
            __syncthreads();
        }
    }

    // ================= mainloop =================
    float best[4], sec[4]; int ibest[4], isec[4];
#pragma unroll
    for (int i = 0; i < 4; i++) { best[i] = -3.0e38f; sec[i] = -3.0e38f; ibest[i] = 0x3fffffff; isec[i] = 0x3fffffff; }

    const uint32_t aHrow = sbase + (uint32_t)((wm * 32 + (lane & 15)) * 144 + (lane >> 4) * 16);
    const uint32_t bRow  = (uint32_t)((wn * 32 + ((lane >> 4) & 1) * 8 + (lane & 7)) * 144 +
                                      ((lane >> 3) & 1) * 16);

#define STAGE_B(s_) do { \
    int nc_ = (s_) >> 2, kc_ = (s_) & 3; \
    uint32_t dstb = sbase + OFF_B + ((s_) & 1) * BSTAGE; \
    const __nv_bfloat16* sH = g_dh16 + (size_t)nc_ * 128 * CDIM + kc_ * 64; \
    const __nv_bfloat16* sM = g_dm16 + (size_t)nc_ * 128 * CDIM + kc_ * 64; \
    _Pragma("unroll") \
    for (int it = 0; it < 2; it++) { \
        int j = tid + it * 512; int d = j >> 3, u = j & 7; \
        CPA16(dstb + d * 144 + u * 16, sH + (size_t)d * CDIM + u * 8); \
        CPA16(dstb + BSTAGE / 2 + d * 144 + u * 16, sM + (size_t)d * CDIM + u * 8); \
    } \
    CPA_COMMIT(); \
} while (0)

    STAGE_B(0); CPA_WAIT0(); __syncthreads();

    float acc[2][4][4];
    for (int s = 0; s < 16; s++) {
        const int nc = s >> 2, kc = s & 3;
        if (kc == 0) {
#pragma unroll
            for (int mt = 0; mt < 2; mt++)
#pragma unroll
                for (int nt = 0; nt < 4; nt++)
#pragma unroll
                    for (int e = 0; e < 4; e++) acc[mt][nt][e] = 0.f;
        }
        if (s < 15) STAGE_B(s + 1);

        const uint32_t aH = aHrow + kc * AK;
        const uint32_t bb = sbase + OFF_B + (s & 1) * BSTAGE + bRow;
        const uint32_t bH = bb, bM = bb + BSTAGE / 2;

#pragma unroll
        for (int ks = 0; ks < 4; ks++) {
            const uint32_t koff = ks * 32;
            uint32_t ah[2][4], bh[4][2], bm[4][2];
            // hoist ALL loads for this ks ahead of the mmas (overlap)
#pragma unroll
            for (int mt = 0; mt < 2; mt++) ldmx4(ah[mt], aH + mt * 2304 + koff);
            {
                uint32_t tp[4];
                ldmx4(tp, bH + koff);        bh[0][0]=tp[0]; bh[0][1]=tp[1]; bh[1][0]=tp[2]; bh[1][1]=tp[3];
                ldmx4(tp, bH + 2304 + koff); bh[2][0]=tp[0]; bh[2][1]=tp[1]; bh[3][0]=tp[2]; bh[3][1]=tp[3];
                ldmx4(tp, bM + koff);        bm[0][0]=tp[0]; bm[0][1]=tp[1]; bm[1][0]=tp[2]; bm[1][1]=tp[3];
                ldmx4(tp, bM + 2304 + koff); bm[2][0]=tp[0]; bm[2][1]=tp[1]; bm[3][0]=tp[2]; bm[3][1]=tp[3];
            }
#pragma unroll
            for (int mt = 0; mt < 2; mt++)
#pragma unroll
                for (int nt = 0; nt < 4; nt++) mma16816(acc[mt][nt], ah[mt], bh[nt]);
#pragma unroll
            for (int mt = 0; mt < 2; mt++)
#pragma unroll
                for (int nt = 0; nt < 4; nt++) mma16816(acc[mt][nt], ah[mt], bm[nt]);
        }

        if (kc == 3) {
            const int dbase = nc * 128 + wn * 32 + (lane & 3) * 2;
#pragma unroll
            for (int mt = 0; mt < 2; mt++) {
#pragma unroll
                for (int rh = 0; rh < 2; rh++) {
                    const int li = mt * 2 + rh;
                    float b_ = best[li], s_ = sec[li]; int bi_ = ibest[li], si_ = isec[li];
#pragma unroll
                    for (int nt = 0; nt < 4; nt++) {
#pragma unroll
                        for (int cc = 0; cc < 2; cc++) {
                            const int d = dbase + nt * 8 + cc;
                            float v = acc[mt][nt][rh * 2 + cc] - shn[d];
                            if (v > b_)      { s_ = b_; si_ = bi_; b_ = v; bi_ = d; }
                            else if (v > s_) { s_ = v;  si_ = d; }
                        }
                    }
                    best[li] = b_; sec[li] = s_; ibest[li] = bi_; isec[li] = si_;
                }
            }
        }
        CPA_WAIT0();
        __syncthreads();
    }

    // ================= cross-thread top-2 merge =================
    {
        float* bestv = smem;                               // [128][16]
        float* secv  = smem + 2048;
        int*   ibv   = reinterpret_cast<int*>(smem + 4096);
        int*   isv   = reinterpret_cast<int*>(smem + 6144);
        const int slot = wn * 4 + (lane & 3);
#pragma unroll
        for (int mt = 0; mt < 2; mt++)
#pragma unroll
            for (int rh = 0; rh < 2; rh++) {
                const int li = mt * 2 + rh;
                const int t = wm * 32 + mt * 16 + (lane >> 2) + rh * 8;
                bestv[t * 16 + slot] = best[li];
                secv [t * 16 + slot] = sec[li];
                ibv  [t * 16 + slot] = ibest[li];
                isv  [t * 16 + slot] = isec[li];
            }
        __syncthreads();

        if (tid < BT) {
            float B = -3.0e38f, S = -3.0e38f; int I = 0x3fffffff, J = 0x3fffffff;
            for (int q = 0; q < 16; q++) {
                float b = bestv[tid * 16 + q], s2 = secv[tid * 16 + q];
                int   i = ibv[tid * 16 + q],   j2 = isv[tid * 16 + q];
                bool bw = (b > B) || (b == B && i < I);
                if (bw) {
                    bool c = (B > s2) || (B == s2 && I < j2);
                    S = c ? B : s2; J = c ? I : j2;
                    B = b; I = i;
                } else {
                    bool c = (b > S) || (b == S && i < J);
                    if (c) { S = b; J = i; }
                }
            }
            fidx[tid] = I; sidxm[tid] = J;
            if (B - S < MARGIN) { int p = atomicAdd(flagn, 1); flags[p] = tid; }
        }
    }
    __syncthreads();

    // ================= exact fp32 rescore for near-tie queries =================
    {
        const int nf = *flagn;
        for (int e = wid; e < nf; e += 16) {
            const int q = flags[e];
            const int i1 = fidx[q], i2 = sidxm[q];
            const float* xp = inputs + ((size_t)n * CDIM) * TDIM + tt0 + q;
            float p1 = 0.f, p2 = 0.f;
            for (int c = lane; c < CDIM; c += 32) {
                float xv = xp[(size_t)c * TDIM];
                p1 += xv * dict[(size_t)i1 * CDIM + c];
                p2 += xv * dict[(size_t)i2 * CDIM + c];
            }
#pragma unroll
            for (int o = 16; o; o >>= 1) {
                p1 += __shfl_xor_sync(0xffffffffu, p1, o);
                p2 += __shfl_xor_sync(0xffffffffu, p2, o);
            }
            if (lane == 0) {
                float c1 = p1 - g_hnorm[i1];
                float c2 = p2 - g_hnorm[i2];
                fidx[q] = (c2 > c1 || (c2 == c1 && i2 < i1)) ? i2 : i1;
            }
        }
    }
    __syncthreads();

    if (tid < BT)
        out[2 * E + (size_t)n * TDIM + tt0 + tid] = (float)fidx[tid];

    // ================= epilogue: gather selected rows, coalesced stores =================
    {
        float* rowsT = smem;   // [256][RT_STRIDE]
        for (int t = wid; t < BT; t += 16) {
            const float* drow = dict + (size_t)fidx[t] * CDIM;
#pragma unroll
            for (int q = 0; q < CDIM; q += 32)
                rowsT[(q + lane) * RT_STRIDE + t] = drow[q + lane];
        }
    }
    __syncthreads();
    {
        const float* rowsT = smem;
        float* out_e = out;
        float* out_p = out + E;
#pragma unroll
        for (int j = 0; j < 16; j++) {
            int c = wid + 16 * j;
            float4 v = *reinterpret_cast<const float4*>(&rowsT[c * RT_STRIDE + 4 * lane]);
            size_t o = ((size_t)n * CDIM + c) * TDIM + tt0 + 4 * lane;
            *reinterpret_cast<float4*>(out_e + o) = v;
            *reinterpret_cast<float4*>(out_p + o) = v;
        }
    }
}

// ---------------------------------------------------------------------------
extern "C" void kernel_launch(void* const* d_in, const int* in_sizes, int n_in,
                              void* d_out, int out_size) {
    const float* inputs = (const float*)d_in[0];
    const float* dict   = (const float*)d_in[1];
    float* out = (float*)d_out;

    cudaFuncSetAttribute(vq_main_kernel,
                         cudaFuncAttributeMaxDynamicSharedMemorySize, SMEM_BYTES);

    vq_hnorm_kernel<<<64, 256>>>(dict);
    vq_split_kernel<<<256, 256>>>(dict);
    vq_main_kernel<<<(NBATCH * TDIM) / BT, NTHREADS, SMEM_BYTES>>>(inputs, dict, out);
}

// round 7
// speedup vs baseline: 1.2035x; 1.2035x over previous
#include <cuda_runtime.h>
#include <cuda_bf16.h>
#include <cstdint>

#define NBATCH 8
#define CDIM   256
#define TDIM   16384
#define DCODES 512
#define BT     128
#define NTHREADS 512
#define MARGIN 0.25f

// ---- smem byte layout ----
// Ah[4 kchunks][128 t][72 bf16-slots]; row stride 144 B
#define AK        18432                 // 128*144
#define OFF_B     73728                 // B double buffer (= 4*AK)
#define BSTAGE    18432                 // per stage: Bh only (128 codes x 144 B)
#define OFF_HN    135680                // float[512] hnorm (above rowsT overlay 135168)
#define OFF_FIDX  137728                // int[128]
#define OFF_BQ    138240                // float[128] approx best per query
#define OFF_FLAGS 138752                // int[128]
#define OFF_FLAGN 139264                // int
#define SMEM_BYTES 139280
// overlays (A region, dead after mainloop): bestv[128][16]@0, secv@8192,
// ibv@16384, isv@24576; later rowsT[256][132] f32 @0 (135168 B)
#define RT_STRIDE 132

__device__ float g_hnorm[DCODES];
__device__ __align__(256) __nv_bfloat16 g_dh16[DCODES * CDIM];

// ---------------- helpers ----------------
__device__ __forceinline__ uint32_t smem_u32(const void* p) {
    uint32_t a;
    asm("{ .reg .u64 t; cvta.to.shared.u64 t, %1; cvt.u32.u64 %0, t; }" : "=r"(a) : "l"(p));
    return a;
}
__device__ __forceinline__ void ldmx4(uint32_t r[4], uint32_t addr) {
    asm volatile("ldmatrix.sync.aligned.m8n8.x4.shared.b16 {%0,%1,%2,%3}, [%4];"
                 : "=r"(r[0]), "=r"(r[1]), "=r"(r[2]), "=r"(r[3]) : "r"(addr));
}
__device__ __forceinline__ void mma16816(float c[4], const uint32_t a[4], const uint32_t b[2]) {
    asm volatile("mma.sync.aligned.m16n8k16.row.col.f32.bf16.bf16.f32 "
                 "{%0,%1,%2,%3}, {%4,%5,%6,%7}, {%8,%9}, {%0,%1,%2,%3};"
                 : "+f"(c[0]), "+f"(c[1]), "+f"(c[2]), "+f"(c[3])
                 : "r"(a[0]), "r"(a[1]), "r"(a[2]), "r"(a[3]), "r"(b[0]), "r"(b[1]));
}
#define CPA16(dst, src) \
    asm volatile("cp.async.cg.shared.global [%0], [%1], 16;" :: "r"(dst), "l"(src) : "memory")
#define CPA_COMMIT() asm volatile("cp.async.commit_group;" ::: "memory")
#define CPA_WAIT0()  asm volatile("cp.async.wait_group 0;" ::: "memory")

// ---------------- prologue kernels ----------------
__global__ void vq_hnorm_kernel(const float* __restrict__ dict) {
    const int wid = threadIdx.x >> 5, lane = threadIdx.x & 31;
    const int d = blockIdx.x * 8 + wid;
    const float4* row = reinterpret_cast<const float4*>(dict + (size_t)d * CDIM);
    float s = 0.f;
#pragma unroll
    for (int j = 0; j < 2; j++) {
        float4 v = row[lane + 32 * j];
        s += v.x * v.x + v.y * v.y + v.z * v.z + v.w * v.w;
    }
#pragma unroll
    for (int o = 16; o; o >>= 1) s += __shfl_xor_sync(0xffffffffu, s, o);
    if (lane == 0) g_hnorm[d] = 0.5f * s;
}

__global__ void vq_split_kernel(const float* __restrict__ dict) {
    int idx = blockIdx.x * blockDim.x + threadIdx.x;   // 0..65535
    int d = idx >> 7, j = idx & 127;
    float x0 = dict[(size_t)d * CDIM + 2 * j];
    float x1 = dict[(size_t)d * CDIM + 2 * j + 1];
    __nv_bfloat162 h2 = __float22bfloat162_rn(make_float2(x0, x1));
    reinterpret_cast<uint32_t*>(g_dh16)[d * 128 + j] = *reinterpret_cast<uint32_t*>(&h2);
}

// ---------------- main kernel ----------------
__global__ __launch_bounds__(NTHREADS, 1)
void vq_main_kernel(const float* __restrict__ inputs,
                    const float* __restrict__ dict,
                    float* __restrict__ out) {
    extern __shared__ float smem[];
    const uint32_t sbase = smem_u32(smem);
    char* smc = reinterpret_cast<char*>(smem);
    float* shn   = reinterpret_cast<float*>(smc + OFF_HN);
    int*   fidx  = reinterpret_cast<int*>(smc + OFF_FIDX);
    float* bq    = reinterpret_cast<float*>(smc + OFF_BQ);
    int*   flags = reinterpret_cast<int*>(smc + OFF_FLAGS);
    int*   flagn = reinterpret_cast<int*>(smc + OFF_FLAGN);

    const int tid = threadIdx.x;
    const int wid = tid >> 5, lane = tid & 31;
    const int wm = wid >> 2, wn = wid & 3;           // 4 x 4 warp grid
    const int n = blockIdx.x >> 7, tt0 = (blockIdx.x & 127) << 7;
    const size_t E = (size_t)NBATCH * CDIM * TDIM;

    if (tid == 0) *flagn = 0;
    if (tid < DCODES) shn[tid] = g_hnorm[tid];

    // ================= A build: load x slabs, transpose + bf16-hi into Ah =================
    {
        float* xsl = smem + OFF_B / 4;     // slab [64 c][128 t] fp32 in B region (32 KB <= 36 KB)
        const int t = tid & 127, quarter = tid >> 7;    // 0..3
        for (int kc = 0; kc < 4; kc++) {
#pragma unroll
            for (int it = 0; it < 4; it++) {
                int j = tid + it * 512;
                int c = j >> 5, u = j & 31;
                const float* src = inputs + ((size_t)(n * CDIM + kc * 64 + c)) * TDIM + tt0 + u * 4;
                CPA16(sbase + OFF_B + c * 512 + u * 16, src);
            }
            CPA_COMMIT(); CPA_WAIT0();
            __syncthreads();
#pragma unroll
            for (int i = 0; i < 8; i++) {
                int c = quarter * 16 + 2 * i;
                float x0 = xsl[c * 128 + t];
                float x1 = xsl[(c + 1) * 128 + t];
                __nv_bfloat162 h2 = __float22bfloat162_rn(make_float2(x0, x1));
                *reinterpret_cast<uint32_t*>(smc + kc * AK + t * 144 + c * 2) =
                    *reinterpret_cast<uint32_t*>(&h2);
            }
            __syncthreads();
        }
    }

    // ================= mainloop (single pass: x_hi * W_hi) =================
    float best[4], sec[4]; int ibest[4], isec[4];
#pragma unroll
    for (int i = 0; i < 4; i++) { best[i] = -3.0e38f; sec[i] = -3.0e38f; ibest[i] = 0x3fffffff; isec[i] = 0x3fffffff; }

    const uint32_t aHrow = sbase + (uint32_t)((wm * 32 + (lane & 15)) * 144 + (lane >> 4) * 16);
    const uint32_t bRow  = (uint32_t)((wn * 32 + ((lane >> 4) & 1) * 8 + (lane & 7)) * 144 +
                                      ((lane >> 3) & 1) * 16);

#define STAGE_B(s_) do { \
    int nc_ = (s_) >> 2, kc_ = (s_) & 3; \
    uint32_t dstb = sbase + OFF_B + ((s_) & 1) * BSTAGE; \
    const __nv_bfloat16* sH = g_dh16 + (size_t)nc_ * 128 * CDIM + kc_ * 64; \
    _Pragma("unroll") \
    for (int it = 0; it < 2; it++) { \
        int j = tid + it * 512; int d = j >> 3, u = j & 7; \
        CPA16(dstb + d * 144 + u * 16, sH + (size_t)d * CDIM + u * 8); \
    } \
    CPA_COMMIT(); \
} while (0)

    STAGE_B(0); CPA_WAIT0(); __syncthreads();

    float acc[2][4][4];
    for (int s = 0; s < 16; s++) {
        const int nc = s >> 2, kc = s & 3;
        if (kc == 0) {
#pragma unroll
            for (int mt = 0; mt < 2; mt++)
#pragma unroll
                for (int nt = 0; nt < 4; nt++)
#pragma unroll
                    for (int e = 0; e < 4; e++) acc[mt][nt][e] = 0.f;
        }
        if (s < 15) STAGE_B(s + 1);

        const uint32_t aH = aHrow + kc * AK;
        const uint32_t bH = sbase + OFF_B + (s & 1) * BSTAGE + bRow;

#pragma unroll
        for (int ks = 0; ks < 4; ks++) {
            const uint32_t koff = ks * 32;
            uint32_t ah[2][4], bh[4][2];
#pragma unroll
            for (int mt = 0; mt < 2; mt++) ldmx4(ah[mt], aH + mt * 2304 + koff);
            {
                uint32_t tp[4];
                ldmx4(tp, bH + koff);        bh[0][0]=tp[0]; bh[0][1]=tp[1]; bh[1][0]=tp[2]; bh[1][1]=tp[3];
                ldmx4(tp, bH + 2304 + koff); bh[2][0]=tp[0]; bh[2][1]=tp[1]; bh[3][0]=tp[2]; bh[3][1]=tp[3];
            }
#pragma unroll
            for (int mt = 0; mt < 2; mt++)
#pragma unroll
                for (int nt = 0; nt < 4; nt++) mma16816(acc[mt][nt], ah[mt], bh[nt]);
        }

        if (kc == 3) {
            const int dbase = nc * 128 + wn * 32 + (lane & 3) * 2;
#pragma unroll
            for (int mt = 0; mt < 2; mt++) {
#pragma unroll
                for (int rh = 0; rh < 2; rh++) {
                    const int li = mt * 2 + rh;
                    float b_ = best[li], s_ = sec[li]; int bi_ = ibest[li], si_ = isec[li];
#pragma unroll
                    for (int nt = 0; nt < 4; nt++) {
#pragma unroll
                        for (int cc = 0; cc < 2; cc++) {
                            const int d = dbase + nt * 8 + cc;
                            float v = acc[mt][nt][rh * 2 + cc] - shn[d];
                            if (v > b_)      { s_ = b_; si_ = bi_; b_ = v; bi_ = d; }
                            else if (v > s_) { s_ = v;  si_ = d; }
                        }
                    }
                    best[li] = b_; sec[li] = s_; ibest[li] = bi_; isec[li] = si_;
                }
            }
        }
        CPA_WAIT0();
        __syncthreads();
    }

    // ================= per-group top-2 publish =================
    float* bestv = smem;                               // [128][16]
    float* secv  = smem + 2048;
    int*   ibv   = reinterpret_cast<int*>(smem + 4096);
    int*   isv   = reinterpret_cast<int*>(smem + 6144);
    {
        const int slot = wn * 4 + (lane & 3);
#pragma unroll
        for (int mt = 0; mt < 2; mt++)
#pragma unroll
            for (int rh = 0; rh < 2; rh++) {
                const int li = mt * 2 + rh;
                const int t = wm * 32 + mt * 16 + (lane >> 2) + rh * 8;
                bestv[t * 16 + slot] = best[li];
                secv [t * 16 + slot] = sec[li];
                ibv  [t * 16 + slot] = ibest[li];
                isv  [t * 16 + slot] = isec[li];
            }
    }
    __syncthreads();

    // ================= approx argmax + candidate flagging =================
    if (tid < BT) {
        float B = -3.0e38f; int I = 0x3fffffff;
#pragma unroll 4
        for (int q = 0; q < 16; q++) {
            float b = bestv[tid * 16 + q];
            int   i = ibv[tid * 16 + q];
            if (b > B || (b == B && i < I)) { B = b; I = i; }
        }
        int ncand = 0;
#pragma unroll 4
        for (int k = 0; k < 32; k++) {
            float s2 = (k < 16) ? bestv[tid * 16 + k] : secv[tid * 16 + (k - 16)];
            int   i2 = (k < 16) ? ibv[tid * 16 + k]   : isv[tid * 16 + (k - 16)];
            if (s2 > B - MARGIN && i2 != I) ncand++;
        }
        fidx[tid] = I; bq[tid] = B;
        if (ncand) { int p = atomicAdd(flagn, 1); flags[p] = tid; }
    }
    __syncthreads();

    // ================= exact fp32 rescore of ALL in-margin candidates =================
    {
        const int nf = *flagn;
        for (int e = wid; e < nf; e += 16) {
            const int q = flags[e];
            const float B = bq[q];
            const float* xp = inputs + ((size_t)n * CDIM) * TDIM + tt0 + q;
            float xr[8];
#pragma unroll
            for (int j = 0; j < 8; j++) xr[j] = xp[(size_t)(lane + 32 * j) * TDIM];
            float bestE = -3.0e38f; int bestI = 0x3fffffff;
            for (int k = 0; k < 32; k++) {
                float s2 = (k < 16) ? bestv[q * 16 + k] : secv[q * 16 + (k - 16)];
                int   i2 = (k < 16) ? ibv[q * 16 + k]   : isv[q * 16 + (k - 16)];
                if (s2 > B - MARGIN) {
                    const float* drow = dict + (size_t)i2 * CDIM;
                    float p = 0.f;
#pragma unroll
                    for (int j = 0; j < 8; j++) p += xr[j] * drow[lane + 32 * j];
#pragma unroll
                    for (int o = 16; o; o >>= 1) p += __shfl_xor_sync(0xffffffffu, p, o);
                    float c = p - shn[i2];
                    if (c > bestE || (c == bestE && i2 < bestI)) { bestE = c; bestI = i2; }
                }
            }
            if (lane == 0) fidx[q] = bestI;
        }
    }
    __syncthreads();

    if (tid < BT)
        out[2 * E + (size_t)n * TDIM + tt0 + tid] = (float)fidx[tid];

    // ================= epilogue: gather selected rows, coalesced stores =================
    {
        float* rowsT = smem;   // [256][RT_STRIDE]
        for (int t = wid; t < BT; t += 16) {
            const float* drow = dict + (size_t)fidx[t] * CDIM;
#pragma unroll
            for (int q = 0; q < CDIM; q += 32)
                rowsT[(q + lane) * RT_STRIDE + t] = drow[q + lane];
        }
    }
    __syncthreads();
    {
        const float* rowsT = smem;
        float* out_e = out;
        float* out_p = out + E;
#pragma unroll
        for (int j = 0; j < 16; j++) {
            int c = wid + 16 * j;
            float4 v = *reinterpret_cast<const float4*>(&rowsT[c * RT_STRIDE + 4 * lane]);
            size_t o = ((size_t)n * CDIM + c) * TDIM + tt0 + 4 * lane;
            *reinterpret_cast<float4*>(out_e + o) = v;
            *reinterpret_cast<float4*>(out_p + o) = v;
        }
    }
}

// ---------------------------------------------------------------------------
extern "C" void kernel_launch(void* const* d_in, const int* in_sizes, int n_in,
                              void* d_out, int out_size) {
    const float* inputs = (const float*)d_in[0];
    const float* dict   = (const float*)d_in[1];
    float* out = (float*)d_out;

    cudaFuncSetAttribute(vq_main_kernel,
                         cudaFuncAttributeMaxDynamicSharedMemorySize, SMEM_BYTES);

    vq_hnorm_kernel<<<64, 256>>>(dict);
    vq_split_kernel<<<256, 256>>>(dict);
    vq_main_kernel<<<(NBATCH * TDIM) / BT, NTHREADS, SMEM_BYTES>>>(inputs, dict, out);
}

// round 8
// speedup vs baseline: 1.3130x; 1.0910x over previous
#include <cuda_runtime.h>
#include <cuda_bf16.h>
#include <cstdint>

#define NBATCH 8
#define CDIM   256
#define TDIM   16384
#define DCODES 512
#define BT     128
#define NTHREADS 256
#define MARGIN 0.25f

// ---- smem byte layout ----
#define AK        18432                 // Ah one kchunk: 128 t x 144 B
#define OFF_B     73728                 // B double buffer (= 4*AK)
#define BSTAGE    18432                 // per stage: 128 codes x 64 c (144 B rows)
#define OFF_HN    110592                // float[512]
#define OFF_FIDX  112640                // int[128]
#define OFF_BQ    113152                // float[128]
#define OFF_FLAGS 113664                // int[128]
#define OFF_FLAGN 114176                // int
#define SMEM_BYTES 114192
// overlays in Ah region (dead post-mainloop): bestv[128][16]@0, secv@8192,
// ibv@16384, isv@24576; epilogue rowsT[64][136] f32 @0 (34816 B)
#define RT_STRIDE 136

__device__ float g_hnorm[DCODES];
__device__ __align__(256) __nv_bfloat16 g_dh16[DCODES * CDIM];

// ---------------- helpers ----------------
__device__ __forceinline__ uint32_t smem_u32(const void* p) {
    uint32_t a;
    asm("{ .reg .u64 t; cvta.to.shared.u64 t, %1; cvt.u32.u64 %0, t; }" : "=r"(a) : "l"(p));
    return a;
}
__device__ __forceinline__ void ldmx4(uint32_t r[4], uint32_t addr) {
    asm volatile("ldmatrix.sync.aligned.m8n8.x4.shared.b16 {%0,%1,%2,%3}, [%4];"
                 : "=r"(r[0]), "=r"(r[1]), "=r"(r[2]), "=r"(r[3]) : "r"(addr));
}
__device__ __forceinline__ void mma16816(float c[4], const uint32_t a[4], const uint32_t b[2]) {
    asm volatile("mma.sync.aligned.m16n8k16.row.col.f32.bf16.bf16.f32 "
                 "{%0,%1,%2,%3}, {%4,%5,%6,%7}, {%8,%9}, {%0,%1,%2,%3};"
                 : "+f"(c[0]), "+f"(c[1]), "+f"(c[2]), "+f"(c[3])
                 : "r"(a[0]), "r"(a[1]), "r"(a[2]), "r"(a[3]), "r"(b[0]), "r"(b[1]));
}
#define CPA16(dst, src) \
    asm volatile("cp.async.cg.shared.global [%0], [%1], 16;" :: "r"(dst), "l"(src) : "memory")
#define CPA_COMMIT() asm volatile("cp.async.commit_group;" ::: "memory")
#define CPA_WAIT0()  asm volatile("cp.async.wait_group 0;" ::: "memory")

// ---------------- merged prologue: hnorm + bf16-hi split ----------------
__global__ void vq_prep_kernel(const float* __restrict__ dict) {
    const int wid = threadIdx.x >> 5, lane = threadIdx.x & 31;
    const int d = blockIdx.x * 8 + wid;
    const float4* row = reinterpret_cast<const float4*>(dict + (size_t)d * CDIM);
    float4 a = row[lane * 2];
    float4 b = row[lane * 2 + 1];
    float s = a.x * a.x + a.y * a.y + a.z * a.z + a.w * a.w
            + b.x * b.x + b.y * b.y + b.z * b.z + b.w * b.w;
#pragma unroll
    for (int o = 16; o; o >>= 1) s += __shfl_xor_sync(0xffffffffu, s, o);
    if (lane == 0) g_hnorm[d] = 0.5f * s;

    __nv_bfloat162 h0 = __float22bfloat162_rn(make_float2(a.x, a.y));
    __nv_bfloat162 h1 = __float22bfloat162_rn(make_float2(a.z, a.w));
    __nv_bfloat162 h2 = __float22bfloat162_rn(make_float2(b.x, b.y));
    __nv_bfloat162 h3 = __float22bfloat162_rn(make_float2(b.z, b.w));
    uint4 v;
    v.x = *reinterpret_cast<uint32_t*>(&h0);
    v.y = *reinterpret_cast<uint32_t*>(&h1);
    v.z = *reinterpret_cast<uint32_t*>(&h2);
    v.w = *reinterpret_cast<uint32_t*>(&h3);
    reinterpret_cast<uint4*>(g_dh16 + (size_t)d * CDIM)[lane] = v;
}

// ---------------- main kernel ----------------
__global__ __launch_bounds__(NTHREADS, 2)
void vq_main_kernel(const float* __restrict__ inputs,
                    const float* __restrict__ dict,
                    float* __restrict__ out) {
    extern __shared__ float smem[];
    const uint32_t sbase = smem_u32(smem);
    char* smc = reinterpret_cast<char*>(smem);
    float* shn   = reinterpret_cast<float*>(smc + OFF_HN);
    int*   fidx  = reinterpret_cast<int*>(smc + OFF_FIDX);
    float* bq    = reinterpret_cast<float*>(smc + OFF_BQ);
    int*   flags = reinterpret_cast<int*>(smc + OFF_FLAGS);
    int*   flagn = reinterpret_cast<int*>(smc + OFF_FLAGN);

    const int tid = threadIdx.x;
    const int wid = tid >> 5, lane = tid & 31;
    const int wm = wid >> 2, wn = wid & 3;           // 2 x 4 warp grid
    const int n = blockIdx.x >> 7, tt0 = (blockIdx.x & 127) << 7;
    const size_t E = (size_t)NBATCH * CDIM * TDIM;

    if (tid == 0) *flagn = 0;
    shn[tid] = g_hnorm[tid];
    shn[tid + 256] = g_hnorm[tid + 256];

    // ================= A build: load x slabs, transpose + bf16-hi into Ah =================
    {
        float* xsl = smem + OFF_B / 4;     // slab [64 c][128 t] fp32 in B region (32 KB)
        const int t = tid & 127, half = tid >> 7;    // 0..1
        for (int kc = 0; kc < 4; kc++) {
#pragma unroll
            for (int it = 0; it < 8; it++) {
                int j = tid + it * 256;
                int c = j >> 5, u = j & 31;
                const float* src = inputs + ((size_t)(n * CDIM + kc * 64 + c)) * TDIM + tt0 + u * 4;
                CPA16(sbase + OFF_B + c * 512 + u * 16, src);
            }
            CPA_COMMIT(); CPA_WAIT0();
            __syncthreads();
#pragma unroll
            for (int i = 0; i < 16; i++) {
                int c = half * 32 + 2 * i;
                float x0 = xsl[c * 128 + t];
                float x1 = xsl[(c + 1) * 128 + t];
                __nv_bfloat162 h2 = __float22bfloat162_rn(make_float2(x0, x1));
                *reinterpret_cast<uint32_t*>(smc + kc * AK + t * 144 + c * 2) =
                    *reinterpret_cast<uint32_t*>(&h2);
            }
            __syncthreads();
        }
    }

    // ================= mainloop (single pass: x_hi * W_hi) =================
    float best[8], sec[8]; int ibest[8], isec[8];
#pragma unroll
    for (int i = 0; i < 8; i++) { best[i] = -3.0e38f; sec[i] = -3.0e38f; ibest[i] = 0x3fffffff; isec[i] = 0x3fffffff; }

    const uint32_t aHrow = sbase + (uint32_t)((wm * 64 + (lane & 15)) * 144 + (lane >> 4) * 16);
    const uint32_t bRow  = (uint32_t)((wn * 32 + ((lane >> 4) & 1) * 8 + (lane & 7)) * 144 +
                                      ((lane >> 3) & 1) * 16);

#define STAGE_B(s_) do { \
    int nc_ = (s_) >> 2, kc_ = (s_) & 3; \
    uint32_t dstb = sbase + OFF_B + ((s_) & 1) * BSTAGE; \
    const __nv_bfloat16* sH = g_dh16 + (size_t)nc_ * 128 * CDIM + kc_ * 64; \
    _Pragma("unroll") \
    for (int it = 0; it < 4; it++) { \
        int j = tid + it * 256; int d = j >> 3, u = j & 7; \
        CPA16(dstb + d * 144 + u * 16, sH + (size_t)d * CDIM + u * 8); \
    } \
    CPA_COMMIT(); \
} while (0)

    STAGE_B(0); CPA_WAIT0(); __syncthreads();

    float acc[4][4][4];
    for (int s = 0; s < 16; s++) {
        const int nc = s >> 2, kc = s & 3;
        if (kc == 0) {
#pragma unroll
            for (int mt = 0; mt < 4; mt++)
#pragma unroll
                for (int nt = 0; nt < 4; nt++)
#pragma unroll
                    for (int e = 0; e < 4; e++) acc[mt][nt][e] = 0.f;
        }
        if (s < 15) STAGE_B(s + 1);

        const uint32_t aH = aHrow + kc * AK;
        const uint32_t bH = sbase + OFF_B + (s & 1) * BSTAGE + bRow;

#pragma unroll
        for (int ks = 0; ks < 4; ks++) {
            const uint32_t koff = ks * 32;
            uint32_t ah[4][4], bh[4][2];
#pragma unroll
            for (int mt = 0; mt < 4; mt++) ldmx4(ah[mt], aH + mt * 2304 + koff);
            {
                uint32_t tp[4];
                ldmx4(tp, bH + koff);        bh[0][0]=tp[0]; bh[0][1]=tp[1]; bh[1][0]=tp[2]; bh[1][1]=tp[3];
                ldmx4(tp, bH + 2304 + koff); bh[2][0]=tp[0]; bh[2][1]=tp[1]; bh[3][0]=tp[2]; bh[3][1]=tp[3];
            }
#pragma unroll
            for (int mt = 0; mt < 4; mt++)
#pragma unroll
                for (int nt = 0; nt < 4; nt++) mma16816(acc[mt][nt], ah[mt], bh[nt]);
        }

        if (kc == 3) {
            const int dbase = nc * 128 + wn * 32 + (lane & 3) * 2;
#pragma unroll
            for (int mt = 0; mt < 4; mt++) {
#pragma unroll
                for (int rh = 0; rh < 2; rh++) {
                    const int li = mt * 2 + rh;
                    float b_ = best[li], s_ = sec[li]; int bi_ = ibest[li], si_ = isec[li];
#pragma unroll
                    for (int nt = 0; nt < 4; nt++) {
#pragma unroll
                        for (int cc = 0; cc < 2; cc++) {
                            const int d = dbase + nt * 8 + cc;
                            float v = acc[mt][nt][rh * 2 + cc] - shn[d];
                            if (v > b_)      { s_ = b_; si_ = bi_; b_ = v; bi_ = d; }
                            else if (v > s_) { s_ = v;  si_ = d; }
                        }
                    }
                    best[li] = b_; sec[li] = s_; ibest[li] = bi_; isec[li] = si_;
                }
            }
        }
        CPA_WAIT0();
        __syncthreads();
    }

    // ================= per-group top-2 publish =================
    float* bestv = smem;                               // [128][16]
    float* secv  = smem + 2048;
    int*   ibv   = reinterpret_cast<int*>(smem + 4096);
    int*   isv   = reinterpret_cast<int*>(smem + 6144);
    {
        const int slot = wn * 4 + (lane & 3);
#pragma unroll
        for (int mt = 0; mt < 4; mt++)
#pragma unroll
            for (int rh = 0; rh < 2; rh++) {
                const int li = mt * 2 + rh;
                const int t = wm * 64 + mt * 16 + (lane >> 2) + rh * 8;
                bestv[t * 16 + slot] = best[li];
                secv [t * 16 + slot] = sec[li];
                ibv  [t * 16 + slot] = ibest[li];
                isv  [t * 16 + slot] = isec[li];
            }
    }
    __syncthreads();

    // ================= approx argmax + candidate flagging =================
    if (tid < BT) {
        float B = -3.0e38f; int I = 0x3fffffff;
#pragma unroll 4
        for (int q = 0; q < 16; q++) {
            float b = bestv[tid * 16 + q];
            int   i = ibv[tid * 16 + q];
            if (b > B || (b == B && i < I)) { B = b; I = i; }
        }
        int ncand = 0;
#pragma unroll 4
        for (int k = 0; k < 32; k++) {
            float s2 = (k < 16) ? bestv[tid * 16 + k] : secv[tid * 16 + (k - 16)];
            int   i2 = (k < 16) ? ibv[tid * 16 + k]   : isv[tid * 16 + (k - 16)];
            if (s2 > B - MARGIN && i2 != I) ncand++;
        }
        fidx[tid] = I; bq[tid] = B;
        if (ncand) { int p = atomicAdd(flagn, 1); flags[p] = tid; }
    }
    __syncthreads();

    // ================= exact fp32 rescore of ALL in-margin candidates =================
    {
        const int nf = *flagn;
        for (int e = wid; e < nf; e += 8) {
            const int q = flags[e];
            const float B = bq[q];
            const float* xp = inputs + ((size_t)n * CDIM) * TDIM + tt0 + q;
            float xr[8];
#pragma unroll
            for (int j = 0; j < 8; j++) xr[j] = xp[(size_t)(lane + 32 * j) * TDIM];
            float bestE = -3.0e38f; int bestI = 0x3fffffff;
            for (int k = 0; k < 32; k++) {
                float s2 = (k < 16) ? bestv[q * 16 + k] : secv[q * 16 + (k - 16)];
                int   i2 = (k < 16) ? ibv[q * 16 + k]   : isv[q * 16 + (k - 16)];
                if (s2 > B - MARGIN) {
                    const float* drow = dict + (size_t)i2 * CDIM;
                    float p = 0.f;
#pragma unroll
                    for (int j = 0; j < 8; j++) p += xr[j] * drow[lane + 32 * j];
#pragma unroll
                    for (int o = 16; o; o >>= 1) p += __shfl_xor_sync(0xffffffffu, p, o);
                    float c = p - shn[i2];
                    if (c > bestE || (c == bestE && i2 < bestI)) { bestE = c; bestI = i2; }
                }
            }
            if (lane == 0) fidx[q] = bestI;
        }
    }
    __syncthreads();

    if (tid < BT)
        out[2 * E + (size_t)n * TDIM + tt0 + tid] = (float)fidx[tid];

    // ================= chunked epilogue: 4 x (gather 64 c, store) =================
    {
        float* rowsT = smem;   // [64 c][RT_STRIDE] overlay of Ah region
        float* out_e = out;
        float* out_p = out + E;
        for (int cc = 0; cc < 4; cc++) {
            __syncthreads();
            for (int t = wid; t < BT; t += 8) {
                const float* drow = dict + (size_t)fidx[t] * CDIM + cc * 64;
                rowsT[lane * RT_STRIDE + t]        = drow[lane];
                rowsT[(lane + 32) * RT_STRIDE + t] = drow[lane + 32];
            }
            __syncthreads();
#pragma unroll
            for (int j = 0; j < 8; j++) {
                int cl = wid + 8 * j;
                float4 v = *reinterpret_cast<const float4*>(&rowsT[cl * RT_STRIDE + 4 * lane]);
                size_t o = ((size_t)n * CDIM + cc * 64 + cl) * TDIM + tt0 + 4 * lane;
                *reinterpret_cast<float4*>(out_e + o) = v;
                *reinterpret_cast<float4*>(out_p + o) = v;
            }
        }
    }
}

// ---------------------------------------------------------------------------
extern "C" void kernel_launch(void* const* d_in, const int* in_sizes, int n_in,
                              void* d_out, int out_size) {
    const float* inputs = (const float*)d_in[0];
    const float* dict   = (const float*)d_in[1];
    float* out = (float*)d_out;

    cudaFuncSetAttribute(vq_main_kernel,
                         cudaFuncAttributeMaxDynamicSharedMemorySize, SMEM_BYTES);

    vq_prep_kernel<<<64, 256>>>(dict);
    vq_main_kernel<<<(NBATCH * TDIM) / BT, NTHREADS, SMEM_BYTES>>>(inputs, dict, out);
}

// round 9
// speedup vs baseline: 1.4918x; 1.1361x over previous
#include <cuda_runtime.h>
#include <cuda_bf16.h>
#include <cstdint>

#define NBATCH 8
#define CDIM   256
#define TDIM   16384
#define DCODES 512
#define BT     128
#define NTHREADS 256
#define MARGIN 0.25f

// ---- smem byte layout ----
#define AK        18432                 // Ah one kchunk: 128 t x 144 B
#define OFF_B     73728                 // B double buffer (= 4*AK)
#define BSTAGE    18432                 // per stage: 128 codes x 64 c (144 B rows)
#define OFF_HN    110592                // float[512]
#define OFF_FIDX  112640                // int[128]
#define OFF_BQ    113152                // float[128]
#define OFF_FLAGS 113664                // int[128]
#define OFF_FLAGN 114176                // int
#define SMEM_BYTES 114192
// overlays in Ah+B region (dead post-mainloop): bestv[128][16]@0, secv@8192,
// ibv@16384, isv@24576 (dead after rescore); epilogue rowsT swizzled 64 KB @0

__device__ float g_hnorm[DCODES];
__device__ __align__(256) __nv_bfloat16 g_dh16[DCODES * CDIM];

// ---------------- helpers ----------------
__device__ __forceinline__ uint32_t smem_u32(const void* p) {
    uint32_t a;
    asm("{ .reg .u64 t; cvta.to.shared.u64 t, %1; cvt.u32.u64 %0, t; }" : "=r"(a) : "l"(p));
    return a;
}
__device__ __forceinline__ void ldmx4(uint32_t r[4], uint32_t addr) {
    asm volatile("ldmatrix.sync.aligned.m8n8.x4.shared.b16 {%0,%1,%2,%3}, [%4];"
                 : "=r"(r[0]), "=r"(r[1]), "=r"(r[2]), "=r"(r[3]) : "r"(addr));
}
__device__ __forceinline__ void mma16816(float c[4], const uint32_t a[4], const uint32_t b[2]) {
    asm volatile("mma.sync.aligned.m16n8k16.row.col.f32.bf16.bf16.f32 "
                 "{%0,%1,%2,%3}, {%4,%5,%6,%7}, {%8,%9}, {%0,%1,%2,%3};"
                 : "+f"(c[0]), "+f"(c[1]), "+f"(c[2]), "+f"(c[3])
                 : "r"(a[0]), "r"(a[1]), "r"(a[2]), "r"(a[3]), "r"(b[0]), "r"(b[1]));
}
#define CPA16(dst, src) \
    asm volatile("cp.async.cg.shared.global [%0], [%1], 16;" :: "r"(dst), "l"(src) : "memory")
#define CPA_COMMIT() asm volatile("cp.async.commit_group;" ::: "memory")
#define CPA_WAIT0()  asm volatile("cp.async.wait_group 0;" ::: "memory")

// swizzled rowsT offset (bytes): conflict-free for STS.128 along t and LDS.128 reads
__device__ __forceinline__ uint32_t rt_off(int c, int t) {
    return (uint32_t)(c * 512 + ((((t >> 2) ^ (c & 31)) << 4) | ((t & 3) << 2)));
}

// ---------------- merged prologue: hnorm + bf16-hi split ----------------
__global__ void vq_prep_kernel(const float* __restrict__ dict) {
    const int wid = threadIdx.x >> 5, lane = threadIdx.x & 31;
    const int d = blockIdx.x * 8 + wid;
    const float4* row = reinterpret_cast<const float4*>(dict + (size_t)d * CDIM);
    float4 a = row[lane * 2];
    float4 b = row[lane * 2 + 1];
    float s = a.x * a.x + a.y * a.y + a.z * a.z + a.w * a.w
            + b.x * b.x + b.y * b.y + b.z * b.z + b.w * b.w;
#pragma unroll
    for (int o = 16; o; o >>= 1) s += __shfl_xor_sync(0xffffffffu, s, o);
    if (lane == 0) g_hnorm[d] = 0.5f * s;

    __nv_bfloat162 h0 = __float22bfloat162_rn(make_float2(a.x, a.y));
    __nv_bfloat162 h1 = __float22bfloat162_rn(make_float2(a.z, a.w));
    __nv_bfloat162 h2 = __float22bfloat162_rn(make_float2(b.x, b.y));
    __nv_bfloat162 h3 = __float22bfloat162_rn(make_float2(b.z, b.w));
    uint4 v;
    v.x = *reinterpret_cast<uint32_t*>(&h0);
    v.y = *reinterpret_cast<uint32_t*>(&h1);
    v.z = *reinterpret_cast<uint32_t*>(&h2);
    v.w = *reinterpret_cast<uint32_t*>(&h3);
    reinterpret_cast<uint4*>(g_dh16 + (size_t)d * CDIM)[lane] = v;
}

// ---------------- main kernel ----------------
__global__ __launch_bounds__(NTHREADS, 2)
void vq_main_kernel(const float* __restrict__ inputs,
                    const float* __restrict__ dict,
                    float* __restrict__ out) {
    extern __shared__ float smem[];
    const uint32_t sbase = smem_u32(smem);
    char* smc = reinterpret_cast<char*>(smem);
    float* shn   = reinterpret_cast<float*>(smc + OFF_HN);
    int*   fidx  = reinterpret_cast<int*>(smc + OFF_FIDX);
    float* bq    = reinterpret_cast<float*>(smc + OFF_BQ);
    int*   flags = reinterpret_cast<int*>(smc + OFF_FLAGS);
    int*   flagn = reinterpret_cast<int*>(smc + OFF_FLAGN);

    const int tid = threadIdx.x;
    const int wid = tid >> 5, lane = tid & 31;
    const int wm = wid >> 2, wn = wid & 3;           // 2 x 4 warp grid
    const int n = blockIdx.x >> 7, tt0 = (blockIdx.x & 127) << 7;
    const size_t E = (size_t)NBATCH * CDIM * TDIM;

    if (tid == 0) *flagn = 0;
    shn[tid] = g_hnorm[tid];
    shn[tid + 256] = g_hnorm[tid + 256];

    // ================= A build: load x slabs, transpose + bf16-hi into Ah =================
    {
        float* xsl = smem + OFF_B / 4;     // slab [64 c][128 t] fp32 in B region (32 KB)
        const int t = tid & 127, half = tid >> 7;    // 0..1
        for (int kc = 0; kc < 4; kc++) {
#pragma unroll
            for (int it = 0; it < 8; it++) {
                int j = tid + it * 256;
                int c = j >> 5, u = j & 31;
                const float* src = inputs + ((size_t)(n * CDIM + kc * 64 + c)) * TDIM + tt0 + u * 4;
                CPA16(sbase + OFF_B + c * 512 + u * 16, src);
            }
            CPA_COMMIT(); CPA_WAIT0();
            __syncthreads();
#pragma unroll
            for (int i = 0; i < 8; i++) {
                int c = half * 32 + 4 * i;
                float x0 = xsl[c * 128 + t];
                float x1 = xsl[(c + 1) * 128 + t];
                float x2 = xsl[(c + 2) * 128 + t];
                float x3 = xsl[(c + 3) * 128 + t];
                __nv_bfloat162 ha = __float22bfloat162_rn(make_float2(x0, x1));
                __nv_bfloat162 hb = __float22bfloat162_rn(make_float2(x2, x3));
                uint2 v;
                v.x = *reinterpret_cast<uint32_t*>(&ha);
                v.y = *reinterpret_cast<uint32_t*>(&hb);
                *reinterpret_cast<uint2*>(smc + kc * AK + t * 144 + c * 2) = v;
            }
            __syncthreads();
        }
    }

    // ================= mainloop (single pass: x_hi * W_hi) =================
    float best[8], sec[8]; int ibest[8], isec[8];
#pragma unroll
    for (int i = 0; i < 8; i++) { best[i] = -3.0e38f; sec[i] = -3.0e38f; ibest[i] = 0x3fffffff; isec[i] = 0x3fffffff; }

    const uint32_t aHrow = sbase + (uint32_t)((wm * 64 + (lane & 15)) * 144 + (lane >> 4) * 16);
    const uint32_t bRow  = (uint32_t)((wn * 32 + ((lane >> 4) & 1) * 8 + (lane & 7)) * 144 +
                                      ((lane >> 3) & 1) * 16);

#define STAGE_B(s_) do { \
    int nc_ = (s_) >> 2, kc_ = (s_) & 3; \
    uint32_t dstb = sbase + OFF_B + ((s_) & 1) * BSTAGE; \
    const __nv_bfloat16* sH = g_dh16 + (size_t)nc_ * 128 * CDIM + kc_ * 64; \
    _Pragma("unroll") \
    for (int it = 0; it < 4; it++) { \
        int j = tid + it * 256; int d = j >> 3, u = j & 7; \
        CPA16(dstb + d * 144 + u * 16, sH + (size_t)d * CDIM + u * 8); \
    } \
    CPA_COMMIT(); \
} while (0)

    STAGE_B(0); CPA_WAIT0(); __syncthreads();

    float acc[4][4][4];
    for (int s = 0; s < 16; s++) {
        const int nc = s >> 2, kc = s & 3;
        if (kc == 0) {
#pragma unroll
            for (int mt = 0; mt < 4; mt++)
#pragma unroll
                for (int nt = 0; nt < 4; nt++)
#pragma unroll
                    for (int e = 0; e < 4; e++) acc[mt][nt][e] = 0.f;
        }
        if (s < 15) STAGE_B(s + 1);

        const uint32_t aH = aHrow + kc * AK;
        const uint32_t bH = sbase + OFF_B + (s & 1) * BSTAGE + bRow;

#pragma unroll
        for (int ks = 0; ks < 4; ks++) {
            const uint32_t koff = ks * 32;
            uint32_t ah[4][4], bh[4][2];
#pragma unroll
            for (int mt = 0; mt < 4; mt++) ldmx4(ah[mt], aH + mt * 2304 + koff);
            {
                uint32_t tp[4];
                ldmx4(tp, bH + koff);        bh[0][0]=tp[0]; bh[0][1]=tp[1]; bh[1][0]=tp[2]; bh[1][1]=tp[3];
                ldmx4(tp, bH + 2304 + koff); bh[2][0]=tp[0]; bh[2][1]=tp[1]; bh[3][0]=tp[2]; bh[3][1]=tp[3];
            }
#pragma unroll
            for (int mt = 0; mt < 4; mt++)
#pragma unroll
                for (int nt = 0; nt < 4; nt++) mma16816(acc[mt][nt], ah[mt], bh[nt]);
        }

        if (kc == 3) {
            const int dbase = nc * 128 + wn * 32 + (lane & 3) * 2;
#pragma unroll
            for (int mt = 0; mt < 4; mt++) {
#pragma unroll
                for (int rh = 0; rh < 2; rh++) {
                    const int li = mt * 2 + rh;
                    float b_ = best[li], s_ = sec[li]; int bi_ = ibest[li], si_ = isec[li];
#pragma unroll
                    for (int nt = 0; nt < 4; nt++) {
#pragma unroll
                        for (int cc = 0; cc < 2; cc++) {
                            const int d = dbase + nt * 8 + cc;
                            float v = acc[mt][nt][rh * 2 + cc] - shn[d];
                            if (v > b_)      { s_ = b_; si_ = bi_; b_ = v; bi_ = d; }
                            else if (v > s_) { s_ = v;  si_ = d; }
                        }
                    }
                    best[li] = b_; sec[li] = s_; ibest[li] = bi_; isec[li] = si_;
                }
            }
        }
        CPA_WAIT0();
        __syncthreads();
    }

    // ================= per-group top-2 publish =================
    float* bestv = smem;                               // [128][16]
    float* secv  = smem + 2048;
    int*   ibv   = reinterpret_cast<int*>(smem + 4096);
    int*   isv   = reinterpret_cast<int*>(smem + 6144);
    {
        const int slot = wn * 4 + (lane & 3);
#pragma unroll
        for (int mt = 0; mt < 4; mt++)
#pragma unroll
            for (int rh = 0; rh < 2; rh++) {
                const int li = mt * 2 + rh;
                const int t = wm * 64 + mt * 16 + (lane >> 2) + rh * 8;
                bestv[t * 16 + slot] = best[li];
                secv [t * 16 + slot] = sec[li];
                ibv  [t * 16 + slot] = ibest[li];
                isv  [t * 16 + slot] = isec[li];
            }
    }
    __syncthreads();

    // ================= approx argmax + candidate flagging =================
    if (tid < BT) {
        float B = -3.0e38f; int I = 0x3fffffff;
#pragma unroll 4
        for (int q = 0; q < 16; q++) {
            float b = bestv[tid * 16 + q];
            int   i = ibv[tid * 16 + q];
            if (b > B || (b == B && i < I)) { B = b; I = i; }
        }
        int ncand = 0;
#pragma unroll 4
        for (int k = 0; k < 32; k++) {
            float s2 = (k < 16) ? bestv[tid * 16 + k] : secv[tid * 16 + (k - 16)];
            int   i2 = (k < 16) ? ibv[tid * 16 + k]   : isv[tid * 16 + (k - 16)];
            if (s2 > B - MARGIN && i2 != I) ncand++;
        }
        fidx[tid] = I; bq[tid] = B;
        if (ncand) { int p = atomicAdd(flagn, 1); flags[p] = tid; }
    }
    __syncthreads();

    // ================= exact fp32 rescore of ALL in-margin candidates =================
    {
        const int nf = *flagn;
        for (int e = wid; e < nf; e += 8) {
            const int q = flags[e];
            const float B = bq[q];
            const float* xp = inputs + ((size_t)n * CDIM) * TDIM + tt0 + q;
            float xr[8];
#pragma unroll
            for (int j = 0; j < 8; j++) xr[j] = xp[(size_t)(lane + 32 * j) * TDIM];
            float bestE = -3.0e38f; int bestI = 0x3fffffff;
            for (int k = 0; k < 32; k++) {
                float s2 = (k < 16) ? bestv[q * 16 + k] : secv[q * 16 + (k - 16)];
                int   i2 = (k < 16) ? ibv[q * 16 + k]   : isv[q * 16 + (k - 16)];
                if (s2 > B - MARGIN) {
                    const float* drow = dict + (size_t)i2 * CDIM;
                    float p = 0.f;
#pragma unroll
                    for (int j = 0; j < 8; j++) p += xr[j] * drow[lane + 32 * j];
#pragma unroll
                    for (int o = 16; o; o >>= 1) p += __shfl_xor_sync(0xffffffffu, p, o);
                    float c = p - shn[i2];
                    if (c > bestE || (c == bestE && i2 < bestI)) { bestE = c; bestI = i2; }
                }
            }
            if (lane == 0) fidx[q] = bestI;
        }
    }
    __syncthreads();

    if (tid < BT)
        out[2 * E + (size_t)n * TDIM + tt0 + tid] = (float)fidx[tid];

    // ================= swizzled conflict-free epilogue: 2 c-halves =================
    {
        float* out_e = out;
        float* out_p = out + E;
        for (int h = 0; h < 2; h++) {
            __syncthreads();   // previous half reads done / rescore tables dead
            // gather: warp owns t-groups g = wid + 8*g4 (4 consecutive t each)
#pragma unroll
            for (int g4 = 0; g4 < 4; g4++) {
                const int g = wid + 8 * g4;
                const float* r0 = dict + (size_t)fidx[4 * g    ] * CDIM + h * 128;
                const float* r1 = dict + (size_t)fidx[4 * g + 1] * CDIM + h * 128;
                const float* r2 = dict + (size_t)fidx[4 * g + 2] * CDIM + h * 128;
                const float* r3 = dict + (size_t)fidx[4 * g + 3] * CDIM + h * 128;
#pragma unroll
                for (int cc = 0; cc < 4; cc++) {
                    const int cl = cc * 32 + lane;
                    float4 v = make_float4(r0[cl], r1[cl], r2[cl], r3[cl]);
                    *reinterpret_cast<float4*>(smc + rt_off(cl, 4 * g)) = v;
                }
            }
            __syncthreads();
            // store: conflict-free LDS.128 + coalesced STG.128 x2
#pragma unroll
            for (int j = 0; j < 16; j++) {
                const int cl = wid + 8 * j;
                float4 v = *reinterpret_cast<const float4*>(smc + rt_off(cl, 4 * lane));
                size_t o = ((size_t)n * CDIM + h * 128 + cl) * TDIM + tt0 + 4 * lane;
                *reinterpret_cast<float4*>(out_e + o) = v;
                *reinterpret_cast<float4*>(out_p + o) = v;
            }
        }
    }
}

// ---------------------------------------------------------------------------
extern "C" void kernel_launch(void* const* d_in, const int* in_sizes, int n_in,
                              void* d_out, int out_size) {
    const float* inputs = (const float*)d_in[0];
    const float* dict   = (const float*)d_in[1];
    float* out = (float*)d_out;

    cudaFuncSetAttribute(vq_main_kernel,
                         cudaFuncAttributeMaxDynamicSharedMemorySize, SMEM_BYTES);

    vq_prep_kernel<<<64, 256>>>(dict);
    vq_main_kernel<<<(NBATCH * TDIM) / BT, NTHREADS, SMEM_BYTES>>>(inputs, dict, out);
}